// round 1
// baseline (speedup 1.0000x reference)
#include <cuda_runtime.h>
#include <cstdint>
#include <cstddef>

#define S_LEN 2048
#define D_EMB 2048
#define NHEAD 16
#define HDIM 64
#define DVDIM 128
#define BATCH 2
#define MROWS (BATCH * S_LEN)   // 4096

// λ_init = 0.8 - 0.6*exp(-0.3*12)
#define LAMBDA_INIT_F 0.78360576653162435f
#define ONE_MINUS_LI_F 0.21639423346837565f

// ---------------- scratch (device globals: no allocation allowed) -------
__device__ float g_Q[(size_t)MROWS * D_EMB];
__device__ float g_K[(size_t)MROWS * D_EMB];
__device__ float g_V[(size_t)MROWS * D_EMB];
__device__ float g_A[(size_t)MROWS * D_EMB];
__device__ float g_lam;

// ---------------- packed f32x2 helpers ----------------------------------
__device__ __forceinline__ unsigned long long dup_f32x2(float a) {
    unsigned long long d;
    asm("mov.b64 %0, {%1, %1};" : "=l"(d) : "f"(a));
    return d;
}
__device__ __forceinline__ void fma_f32x2(unsigned long long& acc,
                                          unsigned long long a,
                                          unsigned long long b) {
    asm("fma.rn.f32x2 %0, %1, %2, %0;" : "+l"(acc) : "l"(a), "l"(b));
}
__device__ __forceinline__ void unpack_f32x2(unsigned long long v, float& lo, float& hi) {
    asm("mov.b64 {%0, %1}, %2;" : "=f"(lo), "=f"(hi) : "l"(v));
}

// ---------------- SGEMM: C = A(MxK) * B(KxN), row-major, 128x128x8 ------
__global__ __launch_bounds__(256, 2)
void sgemm_kernel(const float* __restrict__ A, const float* __restrict__ B,
                  float* __restrict__ C, int M, int N, int K)
{
    __shared__ float As[8][128];
    __shared__ float Bs[8][128];

    const int tid = threadIdx.x;
    const int m0 = blockIdx.y * 128;
    const int n0 = blockIdx.x * 128;
    const int ty = tid >> 4;          // 0..15
    const int tx = tid & 15;          // 0..15

    const int aRow = tid >> 1;        // 0..127
    const int aCol = (tid & 1) << 2;  // 0 or 4
    const int bRow = tid >> 5;        // 0..7
    const int bCol = (tid & 31) << 2; // 0..124

    unsigned long long acc[8][4];
#pragma unroll
    for (int i = 0; i < 8; i++)
#pragma unroll
        for (int j = 0; j < 4; j++) acc[i][j] = 0ull;

    const float* Aptr = A + (size_t)(m0 + aRow) * K + aCol;
    const float* Bptr = B + (size_t)bRow * N + n0 + bCol;

    for (int k0 = 0; k0 < K; k0 += 8) {
        float4 av = *(const float4*)(Aptr + k0);
        float4 bv = *(const float4*)(Bptr + (size_t)k0 * N);
        __syncthreads();
        As[aCol + 0][aRow] = av.x;
        As[aCol + 1][aRow] = av.y;
        As[aCol + 2][aRow] = av.z;
        As[aCol + 3][aRow] = av.w;
        *(float4*)&Bs[bRow][bCol] = bv;
        __syncthreads();

#pragma unroll
        for (int kk = 0; kk < 8; kk++) {
            float4 a0 = *(const float4*)&As[kk][ty * 4];
            float4 a1 = *(const float4*)&As[kk][64 + ty * 4];
            const unsigned long long* pb0 = (const unsigned long long*)&Bs[kk][tx * 4];
            const unsigned long long* pb1 = (const unsigned long long*)&Bs[kk][64 + tx * 4];
            unsigned long long b2[4] = { pb0[0], pb0[1], pb1[0], pb1[1] };
            float af[8] = { a0.x, a0.y, a0.z, a0.w, a1.x, a1.y, a1.z, a1.w };
#pragma unroll
            for (int i = 0; i < 8; i++) {
                unsigned long long ad = dup_f32x2(af[i]);
#pragma unroll
                for (int j = 0; j < 4; j++) fma_f32x2(acc[i][j], ad, b2[j]);
            }
        }
    }

#pragma unroll
    for (int i = 0; i < 8; i++) {
        int row = m0 + ((i < 4) ? (ty * 4 + i) : (64 + ty * 4 + (i - 4)));
        float4 o;
        unpack_f32x2(acc[i][0], o.x, o.y);
        unpack_f32x2(acc[i][1], o.z, o.w);
        *(float4*)&C[(size_t)row * N + n0 + tx * 4] = o;
        unpack_f32x2(acc[i][2], o.x, o.y);
        unpack_f32x2(acc[i][3], o.z, o.w);
        *(float4*)&C[(size_t)row * N + n0 + 64 + tx * 4] = o;
    }
}

// ---------------- RoPE (interleaved) on Q and K, in place ----------------
__global__ void rope_kernel(float* __restrict__ Q, float* __restrict__ K)
{
    const long total = (long)MROWS * (D_EMB / 2);
    const float LN1E4_OVER_32 = 9.210340371976184f / 32.0f;
    for (long p = (long)blockIdx.x * blockDim.x + threadIdx.x; p < total;
         p += (long)gridDim.x * blockDim.x) {
        int pcol = (int)(p & (D_EMB / 2 - 1));     // 0..1023
        long row = p >> 10;                        // D_EMB/2 = 1024
        int s = (int)(row & (S_LEN - 1));
        int j = pcol & 31;                         // pair index within 64-d head
        float inv = expf(-(float)j * LN1E4_OVER_32);
        float ang = (float)s * inv;
        float sn, cs;
        sincosf(ang, &sn, &cs);
        size_t idx = (size_t)row * D_EMB + 2 * pcol;
        float q0 = Q[idx], q1 = Q[idx + 1];
        Q[idx]     = q0 * cs - q1 * sn;
        Q[idx + 1] = q1 * cs + q0 * sn;
        float k0 = K[idx], k1 = K[idx + 1];
        K[idx]     = k0 * cs - k1 * sn;
        K[idx + 1] = k1 * cs + k0 * sn;
    }
}

// ---------------- lambda scalar ------------------------------------------
__global__ void lam_kernel(const float* __restrict__ lq1, const float* __restrict__ lk1,
                           const float* __restrict__ lq2, const float* __restrict__ lk2)
{
    __shared__ float s1[64], s2[64];
    int t = threadIdx.x;
    s1[t] = lq1[t] * lk1[t];
    s2[t] = lq2[t] * lk2[t];
    __syncthreads();
    if (t == 0) {
        float d1 = 0.f, d2 = 0.f;
        for (int i = 0; i < 64; i++) { d1 += s1[i]; d2 += s2[i]; }
        g_lam = expf(d1) - expf(d2) + LAMBDA_INIT_F;
    }
}

// ---------------- fused dual-branch flash attention ----------------------
#define BQ 64
#define BK 64
#define QP 68   // smem pitch (float), keeps 16B alignment, reduces conflicts

#define FLASH_SMEM_FLOATS (6 * 64 * QP + 2 * 64 * 128 + 2 * 64 * 16 + 6 * 64)
#define FLASH_SMEM_BYTES  (FLASH_SMEM_FLOATS * 4)

__global__ __launch_bounds__(256, 1)
void flash_kernel(const float* __restrict__ Q, const float* __restrict__ K,
                  const float* __restrict__ V, const float* __restrict__ lnw,
                  const float* __restrict__ lnb, float* __restrict__ Aout)
{
    extern __shared__ float sm[];
    float* sQ1 = sm;
    float* sQ2 = sQ1 + 64 * QP;
    float* sK1 = sQ2 + 64 * QP;
    float* sK2 = sK1 + 64 * QP;
    float* sP1 = sK2 + 64 * QP;
    float* sP2 = sP1 + 64 * QP;
    float* sV  = sP2 + 64 * QP;      // 64 x 128
    float* sOut = sV + 64 * 128;     // 64 x 128
    float* sPt1 = sOut + 64 * 128;   // 64 x 16
    float* sPt2 = sPt1 + 64 * 16;
    float* sM1 = sPt2 + 64 * 16;
    float* sM2 = sM1 + 64;
    float* sL1 = sM2 + 64;
    float* sL2 = sL1 + 64;
    float* sA1 = sL2 + 64;
    float* sA2 = sA1 + 64;

    const int tid = threadIdx.x;
    const int qt = blockIdx.x;          // 0..31
    const int h  = blockIdx.y;          // 0..15
    const int b  = blockIdx.z;          // 0..1
    const int q0 = qt * BQ;
    const size_t rowBase = (size_t)b * S_LEN;

    // ---- load Q tiles (transposed: sQ[kk][r]) ----
#pragma unroll
    for (int it = 0; it < 4; it++) {
        int f4 = tid + 256 * it;
        int r = f4 >> 4;
        int c4 = (f4 & 15) << 2;
        size_t g = (rowBase + q0 + r) * D_EMB + (size_t)(2 * h) * HDIM + c4;
        float4 v1 = *(const float4*)&Q[g];
        float4 v2 = *(const float4*)&Q[g + HDIM];
        sQ1[(c4 + 0) * QP + r] = v1.x; sQ1[(c4 + 1) * QP + r] = v1.y;
        sQ1[(c4 + 2) * QP + r] = v1.z; sQ1[(c4 + 3) * QP + r] = v1.w;
        sQ2[(c4 + 0) * QP + r] = v2.x; sQ2[(c4 + 1) * QP + r] = v2.y;
        sQ2[(c4 + 2) * QP + r] = v2.z; sQ2[(c4 + 3) * QP + r] = v2.w;
    }
    if (tid < 64)       { sM1[tid] = -1e30f; sL1[tid] = 0.f; }
    else if (tid < 128) { sM2[tid - 64] = -1e30f; sL2[tid - 64] = 0.f; }

    float o1[8][4], o2[8][4];
#pragma unroll
    for (int i = 0; i < 8; i++)
#pragma unroll
        for (int j = 0; j < 4; j++) { o1[i][j] = 0.f; o2[i][j] = 0.f; }

    const int ty = tid >> 4, tx = tid & 15;     // score-phase map (4x4)
    const int orow = (tid >> 5) * 8;            // PV rows
    const int ocol = (tid & 31) * 4;            // PV cols

    for (int kt = 0; kt <= qt; kt++) {
        __syncthreads();  // previous PV / Q+init visible; smem safe to overwrite

        // ---- load K1,K2 (transposed) and V ----
#pragma unroll
        for (int it = 0; it < 4; it++) {
            int f4 = tid + 256 * it;
            int r = f4 >> 4;
            int c4 = (f4 & 15) << 2;
            size_t g = (rowBase + (size_t)kt * BK + r) * D_EMB + (size_t)(2 * h) * HDIM + c4;
            float4 v1 = *(const float4*)&K[g];
            float4 v2 = *(const float4*)&K[g + HDIM];
            sK1[(c4 + 0) * QP + r] = v1.x; sK1[(c4 + 1) * QP + r] = v1.y;
            sK1[(c4 + 2) * QP + r] = v1.z; sK1[(c4 + 3) * QP + r] = v1.w;
            sK2[(c4 + 0) * QP + r] = v2.x; sK2[(c4 + 1) * QP + r] = v2.y;
            sK2[(c4 + 2) * QP + r] = v2.z; sK2[(c4 + 3) * QP + r] = v2.w;
        }
#pragma unroll
        for (int it = 0; it < 8; it++) {
            int f4 = tid + 256 * it;
            int r = f4 >> 5;
            int c4 = (f4 & 31) << 2;
            size_t g = (rowBase + (size_t)kt * BK + r) * D_EMB + (size_t)h * DVDIM + c4;
            *(float4*)&sV[r * 128 + c4] = *(const float4*)&V[g];
        }
        __syncthreads();

        // ---- scores S = Q K^T (both branches) ----
        float s1[4][4], s2[4][4];
#pragma unroll
        for (int i = 0; i < 4; i++)
#pragma unroll
            for (int j = 0; j < 4; j++) { s1[i][j] = 0.f; s2[i][j] = 0.f; }

#pragma unroll 8
        for (int kk = 0; kk < 64; kk++) {
            float4 qa = *(const float4*)&sQ1[kk * QP + ty * 4];
            float4 ka = *(const float4*)&sK1[kk * QP + tx * 4];
            float4 qb = *(const float4*)&sQ2[kk * QP + ty * 4];
            float4 kb = *(const float4*)&sK2[kk * QP + tx * 4];
            float qv1[4] = { qa.x, qa.y, qa.z, qa.w };
            float kv1[4] = { ka.x, ka.y, ka.z, ka.w };
            float qv2[4] = { qb.x, qb.y, qb.z, qb.w };
            float kv2[4] = { kb.x, kb.y, kb.z, kb.w };
#pragma unroll
            for (int i = 0; i < 4; i++)
#pragma unroll
                for (int j = 0; j < 4; j++) {
                    s1[i][j] += qv1[i] * kv1[j];
                    s2[i][j] += qv2[i] * kv2[j];
                }
        }

        // ---- scale, mask, per-thread row max ----
        const bool diag = (kt == qt);
#pragma unroll
        for (int i = 0; i < 4; i++) {
            float m1 = -1e30f, m2 = -1e30f;
#pragma unroll
            for (int j = 0; j < 4; j++) {
                float v1 = s1[i][j] * 0.125f;
                float v2 = s2[i][j] * 0.125f;
                if (diag && (tx * 4 + j) > (ty * 4 + i)) { v1 = -1e30f; v2 = -1e30f; }
                s1[i][j] = v1; s2[i][j] = v2;
                m1 = fmaxf(m1, v1); m2 = fmaxf(m2, v2);
            }
            sPt1[(ty * 4 + i) * 16 + tx] = m1;
            sPt2[(ty * 4 + i) * 16 + tx] = m2;
        }
        __syncthreads();

        // ---- row max reduce, alpha ----
        if (tid < 64) {
            float mo = sM1[tid], mn = mo;
#pragma unroll
            for (int t = 0; t < 16; t++) mn = fmaxf(mn, sPt1[tid * 16 + t]);
            sA1[tid] = expf(mo - mn);
            sM1[tid] = mn;
        } else if (tid < 128) {
            int r = tid - 64;
            float mo = sM2[r], mn = mo;
#pragma unroll
            for (int t = 0; t < 16; t++) mn = fmaxf(mn, sPt2[r * 16 + t]);
            sA2[r] = expf(mo - mn);
            sM2[r] = mn;
        }
        __syncthreads();

        // ---- P = exp(S - m), write transposed, partial row sums ----
#pragma unroll
        for (int i = 0; i < 4; i++) {
            int r = ty * 4 + i;
            float mm1 = sM1[r], mm2 = sM2[r];
            float su1 = 0.f, su2 = 0.f;
#pragma unroll
            for (int j = 0; j < 4; j++) {
                int c = tx * 4 + j;
                float p1 = expf(s1[i][j] - mm1);
                float p2 = expf(s2[i][j] - mm2);
                sP1[c * QP + r] = p1;
                sP2[c * QP + r] = p2;
                su1 += p1; su2 += p2;
            }
            sPt1[r * 16 + tx] = su1;
            sPt2[r * 16 + tx] = su2;
        }
        // rescale O by alpha
#pragma unroll
        for (int i = 0; i < 8; i++) {
            float a1 = sA1[orow + i], a2 = sA2[orow + i];
#pragma unroll
            for (int j = 0; j < 4; j++) { o1[i][j] *= a1; o2[i][j] *= a2; }
        }
        __syncthreads();

        // ---- l update ----
        if (tid < 64) {
            float s = 0.f;
#pragma unroll
            for (int t = 0; t < 16; t++) s += sPt1[tid * 16 + t];
            sL1[tid] = sA1[tid] * sL1[tid] + s;
        } else if (tid < 128) {
            int r = tid - 64;
            float s = 0.f;
#pragma unroll
            for (int t = 0; t < 16; t++) s += sPt2[r * 16 + t];
            sL2[r] = sA2[r] * sL2[r] + s;
        }

        // ---- O += P V ----
#pragma unroll 4
        for (int kk = 0; kk < 64; kk++) {
            float4 pa = *(const float4*)&sP1[kk * QP + orow];
            float4 pb = *(const float4*)&sP1[kk * QP + orow + 4];
            float4 pc = *(const float4*)&sP2[kk * QP + orow];
            float4 pd = *(const float4*)&sP2[kk * QP + orow + 4];
            float4 vv = *(const float4*)&sV[kk * 128 + ocol];
            float p1[8] = { pa.x, pa.y, pa.z, pa.w, pb.x, pb.y, pb.z, pb.w };
            float p2[8] = { pc.x, pc.y, pc.z, pc.w, pd.x, pd.y, pd.z, pd.w };
            float vf[4] = { vv.x, vv.y, vv.z, vv.w };
#pragma unroll
            for (int i = 0; i < 8; i++)
#pragma unroll
                for (int j = 0; j < 4; j++) {
                    o1[i][j] += p1[i] * vf[j];
                    o2[i][j] += p2[i] * vf[j];
                }
        }
    }

    __syncthreads();
    float lam = g_lam;

    // ---- combine: attn1 - lam*attn2 (normalized) ----
#pragma unroll
    for (int i = 0; i < 8; i++) {
        int r = orow + i;
        float inv1 = 1.0f / sL1[r];
        float inv2 = lam / sL2[r];
#pragma unroll
        for (int j = 0; j < 4; j++)
            sOut[r * 128 + ocol + j] = o1[i][j] * inv1 - o2[i][j] * inv2;
    }
    __syncthreads();

    // ---- RMSNorm over 128 dims + scale, write ----
    {
        int r = tid >> 2;
        int q4 = tid & 3;
        float ss = 0.f;
#pragma unroll
        for (int u = 0; u < 32; u++) {
            float v = sOut[r * 128 + q4 * 32 + u];
            ss += v * v;
        }
        ss += __shfl_xor_sync(0xffffffffu, ss, 1, 4);
        ss += __shfl_xor_sync(0xffffffffu, ss, 2, 4);
        float rn = rsqrtf(ss * (1.0f / 128.0f) + 1e-8f);
        size_t outrow = (rowBase + q0 + r) * D_EMB + (size_t)h * DVDIM;
#pragma unroll
        for (int u = 0; u < 32; u++) {
            int e = q4 * 32 + u;
            Aout[outrow + e] = (sOut[r * 128 + e] * rn * lnw[e] + lnb[e]) * ONE_MINUS_LI_F;
        }
    }
}

// ---------------- launch ---------------------------------------------------
extern "C" void kernel_launch(void* const* d_in, const int* in_sizes, int n_in,
                              void* d_out, int out_size)
{
    (void)in_sizes; (void)n_in; (void)out_size;
    const float* x   = (const float*)d_in[0];
    const float* Wq  = (const float*)d_in[1];
    const float* Wk  = (const float*)d_in[2];
    const float* Wv  = (const float*)d_in[3];
    const float* Wo  = (const float*)d_in[4];
    const float* lq1 = (const float*)d_in[5];
    const float* lk1 = (const float*)d_in[6];
    const float* lq2 = (const float*)d_in[7];
    const float* lk2 = (const float*)d_in[8];
    const float* lnw = (const float*)d_in[9];
    const float* lnb = (const float*)d_in[10];
    float* out = (float*)d_out;

    float *qp, *kp, *vp, *ap;
    cudaGetSymbolAddress((void**)&qp, g_Q);
    cudaGetSymbolAddress((void**)&kp, g_K);
    cudaGetSymbolAddress((void**)&vp, g_V);
    cudaGetSymbolAddress((void**)&ap, g_A);

    dim3 gg(D_EMB / 128, MROWS / 128);   // (16, 32)

    sgemm_kernel<<<gg, 256>>>(x, Wq, qp, MROWS, D_EMB, D_EMB);
    sgemm_kernel<<<gg, 256>>>(x, Wk, kp, MROWS, D_EMB, D_EMB);
    sgemm_kernel<<<gg, 256>>>(x, Wv, vp, MROWS, D_EMB, D_EMB);

    rope_kernel<<<2048, 256>>>(qp, kp);
    lam_kernel<<<1, 64>>>(lq1, lk1, lq2, lk2);

    cudaFuncSetAttribute(flash_kernel, cudaFuncAttributeMaxDynamicSharedMemorySize,
                         FLASH_SMEM_BYTES);
    flash_kernel<<<dim3(32, NHEAD, BATCH), 256, FLASH_SMEM_BYTES>>>(qp, kp, vp, lnw, lnb, ap);

    sgemm_kernel<<<gg, 256>>>(ap, Wo, out, MROWS, D_EMB, D_EMB);
}

// round 2
// speedup vs baseline: 1.4653x; 1.4653x over previous
#include <cuda_runtime.h>
#include <cuda_bf16.h>
#include <cstdint>
#include <cstddef>

#define S_LEN 2048
#define D_EMB 2048
#define NHEAD 16
#define HDIM 64
#define DVDIM 128
#define BATCH 2
#define MROWS (BATCH * S_LEN)   // 4096

// λ_init = 0.8 - 0.6*exp(-0.3*12)
#define LAMBDA_INIT_F 0.78360576653162435f
#define ONE_MINUS_LI_F 0.21639423346837565f

// ---------------- scratch (device globals: no allocation allowed) -------
__device__ float g_Q[(size_t)MROWS * D_EMB];
__device__ float g_K[(size_t)MROWS * D_EMB];
__device__ float g_V[(size_t)MROWS * D_EMB];
__device__ float g_A[(size_t)MROWS * D_EMB];
__device__ float g_lam;

// bf16 split buffers
__device__ __nv_bfloat16 g_xhi[(size_t)MROWS * D_EMB];
__device__ __nv_bfloat16 g_xlo[(size_t)MROWS * D_EMB];
__device__ __nv_bfloat16 g_whi[4][(size_t)D_EMB * D_EMB];
__device__ __nv_bfloat16 g_wlo[4][(size_t)D_EMB * D_EMB];
__device__ __nv_bfloat16 g_ahi[(size_t)MROWS * D_EMB];
__device__ __nv_bfloat16 g_alo[(size_t)MROWS * D_EMB];

// =================== fp32 -> (bf16 hi, bf16 lo) split ====================
__global__ void split_kernel(const float* __restrict__ in,
                             __nv_bfloat16* __restrict__ hi,
                             __nv_bfloat16* __restrict__ lo, int n4)
{
    int i = blockIdx.x * blockDim.x + threadIdx.x;
    if (i >= n4) return;
    float4 v = ((const float4*)in)[i];
    __nv_bfloat16 hx = __float2bfloat16(v.x);
    __nv_bfloat16 hy = __float2bfloat16(v.y);
    __nv_bfloat16 hz = __float2bfloat16(v.z);
    __nv_bfloat16 hw = __float2bfloat16(v.w);
    __nv_bfloat16 lx = __float2bfloat16(v.x - __bfloat162float(hx));
    __nv_bfloat16 ly = __float2bfloat16(v.y - __bfloat162float(hy));
    __nv_bfloat16 lz = __float2bfloat16(v.z - __bfloat162float(hz));
    __nv_bfloat16 lw = __float2bfloat16(v.w - __bfloat162float(hw));
    __nv_bfloat162* H = (__nv_bfloat162*)hi;
    __nv_bfloat162* L = (__nv_bfloat162*)lo;
    H[2 * i]     = __halves2bfloat162(hx, hy);
    H[2 * i + 1] = __halves2bfloat162(hz, hw);
    L[2 * i]     = __halves2bfloat162(lx, ly);
    L[2 * i + 1] = __halves2bfloat162(lz, lw);
}

// =================== tensor-core GEMM (bf16 x3 split) ====================
// C[M,N] = A[M,K] * B[K,N], fp32 out. A,B given as bf16 hi/lo pairs.
#define BM 128
#define BN 128
#define BK 16
#define A_PITCH_B 48     // bytes per A smem row (24 bf16)
#define B_PITCH_B 272    // bytes per B smem row (136 bf16)
#define OFF_AHI 0
#define OFF_ALO (BM * A_PITCH_B)                 // 6144
#define OFF_BHI (2 * BM * A_PITCH_B)             // 12288
#define OFF_BLO (OFF_BHI + BK * B_PITCH_B)       // 16640
#define STAGE_BYTES (OFF_BLO + BK * B_PITCH_B)   // 20992

__device__ __forceinline__ uint32_t smem_u32(const void* p) {
    return (uint32_t)__cvta_generic_to_shared(p);
}
__device__ __forceinline__ void cp16(uint32_t s, const void* g) {
    asm volatile("cp.async.ca.shared.global [%0], [%1], 16;" :: "r"(s), "l"(g));
}
__device__ __forceinline__ void ldmx4(uint32_t r[4], uint32_t addr) {
    asm volatile("ldmatrix.sync.aligned.m8n8.x4.shared.b16 {%0,%1,%2,%3}, [%4];"
        : "=r"(r[0]), "=r"(r[1]), "=r"(r[2]), "=r"(r[3]) : "r"(addr));
}
__device__ __forceinline__ void ldmx2t(uint32_t r[2], uint32_t addr) {
    asm volatile("ldmatrix.sync.aligned.m8n8.x2.trans.shared.b16 {%0,%1}, [%2];"
        : "=r"(r[0]), "=r"(r[1]) : "r"(addr));
}
__device__ __forceinline__ void mma_bf16(float c[4], const uint32_t a[4], const uint32_t b[2]) {
    asm volatile("mma.sync.aligned.m16n8k16.row.col.f32.bf16.bf16.f32 "
        "{%0,%1,%2,%3}, {%4,%5,%6,%7}, {%8,%9}, {%0,%1,%2,%3};"
        : "+f"(c[0]), "+f"(c[1]), "+f"(c[2]), "+f"(c[3])
        : "r"(a[0]), "r"(a[1]), "r"(a[2]), "r"(a[3]), "r"(b[0]), "r"(b[1]));
}

__global__ __launch_bounds__(256)
void gemm_bf16x3(const __nv_bfloat16* __restrict__ Ahi, const __nv_bfloat16* __restrict__ Alo,
                 const __nv_bfloat16* __restrict__ Bhi, const __nv_bfloat16* __restrict__ Blo,
                 float* __restrict__ C, int M, int N, int K)
{
    __shared__ __align__(16) uint8_t sm[2][STAGE_BYTES];
    const int tid = threadIdx.x;
    const int m0 = blockIdx.y * BM;
    const int n0 = blockIdx.x * BN;
    const uint32_t sbase = smem_u32(&sm[0][0]);

    // cp.async thread mapping: A 256 chunks (128 rows x 2), B 256 (16 rows x 16)
    const int a_r = tid >> 1;
    const int a_c = (tid & 1) * 8;       // bf16 elems
    const int b_r = tid >> 4;
    const int b_c = (tid & 15) * 8;

    const __nv_bfloat16* gAhi = Ahi + (size_t)(m0 + a_r) * K + a_c;
    const __nv_bfloat16* gAlo = Alo + (size_t)(m0 + a_r) * K + a_c;
    const __nv_bfloat16* gBhi = Bhi + (size_t)b_r * N + n0 + b_c;
    const __nv_bfloat16* gBlo = Blo + (size_t)b_r * N + n0 + b_c;
    const uint32_t sA_off = a_r * A_PITCH_B + a_c * 2;
    const uint32_t sB_off = b_r * B_PITCH_B + b_c * 2;

    const int lane = tid & 31;
    const int wid = tid >> 5;
    const int wm = wid & 3;      // 4 warps in M (32 rows each)
    const int wn = wid >> 2;     // 2 warps in N (64 cols each)

    // ldmatrix addresses
    const int ar = wm * 32 + (lane & 7) + ((lane >> 3) & 1) * 8;
    const int ak = ((lane >> 4) & 1) * 8;
    const uint32_t aoff0 = ar * A_PITCH_B + ak * 2;
    const uint32_t aoff1 = aoff0 + 16 * A_PITCH_B;
    const uint32_t boff = (lane & 15) * B_PITCH_B + (wn * 64) * 2;

    float acc[2][8][4];
#pragma unroll
    for (int i = 0; i < 2; i++)
#pragma unroll
        for (int j = 0; j < 8; j++)
#pragma unroll
            for (int l = 0; l < 4; l++) acc[i][j][l] = 0.f;

    const int KT = K / BK;

    // prologue: stage 0
    {
        uint32_t s = sbase;
        cp16(s + OFF_AHI + sA_off, gAhi);
        cp16(s + OFF_ALO + sA_off, gAlo);
        cp16(s + OFF_BHI + sB_off, gBhi);
        cp16(s + OFF_BLO + sB_off, gBlo);
        asm volatile("cp.async.commit_group;");
    }

    for (int t = 0; t < KT; t++) {
        if (t + 1 < KT) {
            uint32_t s = sbase + ((t + 1) & 1) * STAGE_BYTES;
            cp16(s + OFF_AHI + sA_off, gAhi + (size_t)(t + 1) * BK);
            cp16(s + OFF_ALO + sA_off, gAlo + (size_t)(t + 1) * BK);
            cp16(s + OFF_BHI + sB_off, gBhi + (size_t)(t + 1) * BK * N);
            cp16(s + OFF_BLO + sB_off, gBlo + (size_t)(t + 1) * BK * N);
            asm volatile("cp.async.commit_group;");
            asm volatile("cp.async.wait_group 1;");
        } else {
            asm volatile("cp.async.wait_group 0;");
        }
        __syncthreads();

        uint32_t s = sbase + (t & 1) * STAGE_BYTES;
        uint32_t ah[2][4], al[2][4], bh[8][2], bl[8][2];
        ldmx4(ah[0], s + OFF_AHI + aoff0);
        ldmx4(ah[1], s + OFF_AHI + aoff1);
        ldmx4(al[0], s + OFF_ALO + aoff0);
        ldmx4(al[1], s + OFF_ALO + aoff1);
#pragma unroll
        for (int nt = 0; nt < 8; nt++) {
            ldmx2t(bh[nt], s + OFF_BHI + boff + nt * 16);
            ldmx2t(bl[nt], s + OFF_BLO + boff + nt * 16);
        }
#pragma unroll
        for (int mt = 0; mt < 2; mt++)
#pragma unroll
            for (int nt = 0; nt < 8; nt++) {
                mma_bf16(acc[mt][nt], ah[mt], bh[nt]);
                mma_bf16(acc[mt][nt], ah[mt], bl[nt]);
                mma_bf16(acc[mt][nt], al[mt], bh[nt]);
            }
        __syncthreads();
    }

    // epilogue
    const int gid = lane >> 2, tig = lane & 3;
#pragma unroll
    for (int mt = 0; mt < 2; mt++) {
        int row = m0 + wm * 32 + mt * 16 + gid;
#pragma unroll
        for (int nt = 0; nt < 8; nt++) {
            int col = n0 + wn * 64 + nt * 8 + 2 * tig;
            *(float2*)&C[(size_t)row * N + col] = make_float2(acc[mt][nt][0], acc[mt][nt][1]);
            *(float2*)&C[(size_t)(row + 8) * N + col] = make_float2(acc[mt][nt][2], acc[mt][nt][3]);
        }
    }
}

// ---------------- RoPE (interleaved) on Q and K, in place ----------------
__global__ void rope_kernel(float* __restrict__ Q, float* __restrict__ K)
{
    const long total = (long)MROWS * (D_EMB / 2);
    const float LN1E4_OVER_32 = 9.210340371976184f / 32.0f;
    for (long p = (long)blockIdx.x * blockDim.x + threadIdx.x; p < total;
         p += (long)gridDim.x * blockDim.x) {
        int pcol = (int)(p & (D_EMB / 2 - 1));
        long row = p >> 10;
        int s = (int)(row & (S_LEN - 1));
        int j = pcol & 31;
        float inv = expf(-(float)j * LN1E4_OVER_32);
        float ang = (float)s * inv;
        float sn, cs;
        sincosf(ang, &sn, &cs);
        size_t idx = (size_t)row * D_EMB + 2 * pcol;
        float q0 = Q[idx], q1 = Q[idx + 1];
        Q[idx]     = q0 * cs - q1 * sn;
        Q[idx + 1] = q1 * cs + q0 * sn;
        float k0 = K[idx], k1 = K[idx + 1];
        K[idx]     = k0 * cs - k1 * sn;
        K[idx + 1] = k1 * cs + k0 * sn;
    }
}

// ---------------- lambda scalar ------------------------------------------
__global__ void lam_kernel(const float* __restrict__ lq1, const float* __restrict__ lk1,
                           const float* __restrict__ lq2, const float* __restrict__ lk2)
{
    __shared__ float s1[64], s2[64];
    int t = threadIdx.x;
    s1[t] = lq1[t] * lk1[t];
    s2[t] = lq2[t] * lk2[t];
    __syncthreads();
    if (t == 0) {
        float d1 = 0.f, d2 = 0.f;
        for (int i = 0; i < 64; i++) { d1 += s1[i]; d2 += s2[i]; }
        g_lam = expf(d1) - expf(d2) + LAMBDA_INIT_F;
    }
}

// ---------------- fused dual-branch flash attention ----------------------
#define BQ 64
#define BKT 64
#define QP 68

#define FLASH_SMEM_FLOATS (6 * 64 * QP + 2 * 64 * 128 + 2 * 64 * 16 + 6 * 64)
#define FLASH_SMEM_BYTES  (FLASH_SMEM_FLOATS * 4)

__global__ __launch_bounds__(256, 1)
void flash_kernel(const float* __restrict__ Q, const float* __restrict__ K,
                  const float* __restrict__ V, const float* __restrict__ lnw,
                  const float* __restrict__ lnb, float* __restrict__ Aout)
{
    extern __shared__ float smf[];
    float* sQ1 = smf;
    float* sQ2 = sQ1 + 64 * QP;
    float* sK1 = sQ2 + 64 * QP;
    float* sK2 = sK1 + 64 * QP;
    float* sP1 = sK2 + 64 * QP;
    float* sP2 = sP1 + 64 * QP;
    float* sV  = sP2 + 64 * QP;
    float* sOut = sV + 64 * 128;
    float* sPt1 = sOut + 64 * 128;
    float* sPt2 = sPt1 + 64 * 16;
    float* sM1 = sPt2 + 64 * 16;
    float* sM2 = sM1 + 64;
    float* sL1 = sM2 + 64;
    float* sL2 = sL1 + 64;
    float* sA1 = sL2 + 64;
    float* sA2 = sA1 + 64;

    const int tid = threadIdx.x;
    const int qt = blockIdx.x;
    const int h  = blockIdx.y;
    const int b  = blockIdx.z;
    const int q0 = qt * BQ;
    const size_t rowBase = (size_t)b * S_LEN;

#pragma unroll
    for (int it = 0; it < 4; it++) {
        int f4 = tid + 256 * it;
        int r = f4 >> 4;
        int c4 = (f4 & 15) << 2;
        size_t g = (rowBase + q0 + r) * D_EMB + (size_t)(2 * h) * HDIM + c4;
        float4 v1 = *(const float4*)&Q[g];
        float4 v2 = *(const float4*)&Q[g + HDIM];
        sQ1[(c4 + 0) * QP + r] = v1.x; sQ1[(c4 + 1) * QP + r] = v1.y;
        sQ1[(c4 + 2) * QP + r] = v1.z; sQ1[(c4 + 3) * QP + r] = v1.w;
        sQ2[(c4 + 0) * QP + r] = v2.x; sQ2[(c4 + 1) * QP + r] = v2.y;
        sQ2[(c4 + 2) * QP + r] = v2.z; sQ2[(c4 + 3) * QP + r] = v2.w;
    }
    if (tid < 64)       { sM1[tid] = -1e30f; sL1[tid] = 0.f; }
    else if (tid < 128) { sM2[tid - 64] = -1e30f; sL2[tid - 64] = 0.f; }

    float o1[8][4], o2[8][4];
#pragma unroll
    for (int i = 0; i < 8; i++)
#pragma unroll
        for (int j = 0; j < 4; j++) { o1[i][j] = 0.f; o2[i][j] = 0.f; }

    const int ty = tid >> 4, tx = tid & 15;
    const int orow = (tid >> 5) * 8;
    const int ocol = (tid & 31) * 4;

    for (int kt = 0; kt <= qt; kt++) {
        __syncthreads();

#pragma unroll
        for (int it = 0; it < 4; it++) {
            int f4 = tid + 256 * it;
            int r = f4 >> 4;
            int c4 = (f4 & 15) << 2;
            size_t g = (rowBase + (size_t)kt * BKT + r) * D_EMB + (size_t)(2 * h) * HDIM + c4;
            float4 v1 = *(const float4*)&K[g];
            float4 v2 = *(const float4*)&K[g + HDIM];
            sK1[(c4 + 0) * QP + r] = v1.x; sK1[(c4 + 1) * QP + r] = v1.y;
            sK1[(c4 + 2) * QP + r] = v1.z; sK1[(c4 + 3) * QP + r] = v1.w;
            sK2[(c4 + 0) * QP + r] = v2.x; sK2[(c4 + 1) * QP + r] = v2.y;
            sK2[(c4 + 2) * QP + r] = v2.z; sK2[(c4 + 3) * QP + r] = v2.w;
        }
#pragma unroll
        for (int it = 0; it < 8; it++) {
            int f4 = tid + 256 * it;
            int r = f4 >> 5;
            int c4 = (f4 & 31) << 2;
            size_t g = (rowBase + (size_t)kt * BKT + r) * D_EMB + (size_t)h * DVDIM + c4;
            *(float4*)&sV[r * 128 + c4] = *(const float4*)&V[g];
        }
        __syncthreads();

        float s1[4][4], s2[4][4];
#pragma unroll
        for (int i = 0; i < 4; i++)
#pragma unroll
            for (int j = 0; j < 4; j++) { s1[i][j] = 0.f; s2[i][j] = 0.f; }

#pragma unroll 8
        for (int kk = 0; kk < 64; kk++) {
            float4 qa = *(const float4*)&sQ1[kk * QP + ty * 4];
            float4 ka = *(const float4*)&sK1[kk * QP + tx * 4];
            float4 qb = *(const float4*)&sQ2[kk * QP + ty * 4];
            float4 kb = *(const float4*)&sK2[kk * QP + tx * 4];
            float qv1[4] = { qa.x, qa.y, qa.z, qa.w };
            float kv1[4] = { ka.x, ka.y, ka.z, ka.w };
            float qv2[4] = { qb.x, qb.y, qb.z, qb.w };
            float kv2[4] = { kb.x, kb.y, kb.z, kb.w };
#pragma unroll
            for (int i = 0; i < 4; i++)
#pragma unroll
                for (int j = 0; j < 4; j++) {
                    s1[i][j] += qv1[i] * kv1[j];
                    s2[i][j] += qv2[i] * kv2[j];
                }
        }

        const bool diag = (kt == qt);
#pragma unroll
        for (int i = 0; i < 4; i++) {
            float m1 = -1e30f, m2 = -1e30f;
#pragma unroll
            for (int j = 0; j < 4; j++) {
                float v1 = s1[i][j] * 0.125f;
                float v2 = s2[i][j] * 0.125f;
                if (diag && (tx * 4 + j) > (ty * 4 + i)) { v1 = -1e30f; v2 = -1e30f; }
                s1[i][j] = v1; s2[i][j] = v2;
                m1 = fmaxf(m1, v1); m2 = fmaxf(m2, v2);
            }
            sPt1[(ty * 4 + i) * 16 + tx] = m1;
            sPt2[(ty * 4 + i) * 16 + tx] = m2;
        }
        __syncthreads();

        if (tid < 64) {
            float mo = sM1[tid], mn = mo;
#pragma unroll
            for (int t = 0; t < 16; t++) mn = fmaxf(mn, sPt1[tid * 16 + t]);
            sA1[tid] = expf(mo - mn);
            sM1[tid] = mn;
        } else if (tid < 128) {
            int r = tid - 64;
            float mo = sM2[r], mn = mo;
#pragma unroll
            for (int t = 0; t < 16; t++) mn = fmaxf(mn, sPt2[r * 16 + t]);
            sA2[r] = expf(mo - mn);
            sM2[r] = mn;
        }
        __syncthreads();

#pragma unroll
        for (int i = 0; i < 4; i++) {
            int r = ty * 4 + i;
            float mm1 = sM1[r], mm2 = sM2[r];
            float su1 = 0.f, su2 = 0.f;
#pragma unroll
            for (int j = 0; j < 4; j++) {
                int c = tx * 4 + j;
                float p1 = expf(s1[i][j] - mm1);
                float p2 = expf(s2[i][j] - mm2);
                sP1[c * QP + r] = p1;
                sP2[c * QP + r] = p2;
                su1 += p1; su2 += p2;
            }
            sPt1[r * 16 + tx] = su1;
            sPt2[r * 16 + tx] = su2;
        }
#pragma unroll
        for (int i = 0; i < 8; i++) {
            float a1 = sA1[orow + i], a2 = sA2[orow + i];
#pragma unroll
            for (int j = 0; j < 4; j++) { o1[i][j] *= a1; o2[i][j] *= a2; }
        }
        __syncthreads();

        if (tid < 64) {
            float s = 0.f;
#pragma unroll
            for (int t = 0; t < 16; t++) s += sPt1[tid * 16 + t];
            sL1[tid] = sA1[tid] * sL1[tid] + s;
        } else if (tid < 128) {
            int r = tid - 64;
            float s = 0.f;
#pragma unroll
            for (int t = 0; t < 16; t++) s += sPt2[r * 16 + t];
            sL2[r] = sA2[r] * sL2[r] + s;
        }

#pragma unroll 4
        for (int kk = 0; kk < 64; kk++) {
            float4 pa = *(const float4*)&sP1[kk * QP + orow];
            float4 pb = *(const float4*)&sP1[kk * QP + orow + 4];
            float4 pc = *(const float4*)&sP2[kk * QP + orow];
            float4 pd = *(const float4*)&sP2[kk * QP + orow + 4];
            float4 vv = *(const float4*)&sV[kk * 128 + ocol];
            float p1[8] = { pa.x, pa.y, pa.z, pa.w, pb.x, pb.y, pb.z, pb.w };
            float p2[8] = { pc.x, pc.y, pc.z, pc.w, pd.x, pd.y, pd.z, pd.w };
            float vf[4] = { vv.x, vv.y, vv.z, vv.w };
#pragma unroll
            for (int i = 0; i < 8; i++)
#pragma unroll
                for (int j = 0; j < 4; j++) {
                    o1[i][j] += p1[i] * vf[j];
                    o2[i][j] += p2[i] * vf[j];
                }
        }
    }

    __syncthreads();
    float lam = g_lam;

#pragma unroll
    for (int i = 0; i < 8; i++) {
        int r = orow + i;
        float inv1 = 1.0f / sL1[r];
        float inv2 = lam / sL2[r];
#pragma unroll
        for (int j = 0; j < 4; j++)
            sOut[r * 128 + ocol + j] = o1[i][j] * inv1 - o2[i][j] * inv2;
    }
    __syncthreads();

    {
        int r = tid >> 2;
        int q4 = tid & 3;
        float ss = 0.f;
#pragma unroll
        for (int u = 0; u < 32; u++) {
            float v = sOut[r * 128 + q4 * 32 + u];
            ss += v * v;
        }
        ss += __shfl_xor_sync(0xffffffffu, ss, 1, 4);
        ss += __shfl_xor_sync(0xffffffffu, ss, 2, 4);
        float rn = rsqrtf(ss * (1.0f / 128.0f) + 1e-8f);
        size_t outrow = (rowBase + q0 + r) * D_EMB + (size_t)h * DVDIM;
#pragma unroll
        for (int u = 0; u < 32; u++) {
            int e = q4 * 32 + u;
            Aout[outrow + e] = (sOut[r * 128 + e] * rn * lnw[e] + lnb[e]) * ONE_MINUS_LI_F;
        }
    }
}

// ---------------- launch ---------------------------------------------------
extern "C" void kernel_launch(void* const* d_in, const int* in_sizes, int n_in,
                              void* d_out, int out_size)
{
    (void)in_sizes; (void)n_in; (void)out_size;
    const float* x   = (const float*)d_in[0];
    const float* Wq  = (const float*)d_in[1];
    const float* Wk  = (const float*)d_in[2];
    const float* Wv  = (const float*)d_in[3];
    const float* Wo  = (const float*)d_in[4];
    const float* lq1 = (const float*)d_in[5];
    const float* lk1 = (const float*)d_in[6];
    const float* lq2 = (const float*)d_in[7];
    const float* lk2 = (const float*)d_in[8];
    const float* lnw = (const float*)d_in[9];
    const float* lnb = (const float*)d_in[10];
    float* out = (float*)d_out;

    float *qp, *kp, *vp, *ap;
    cudaGetSymbolAddress((void**)&qp, g_Q);
    cudaGetSymbolAddress((void**)&kp, g_K);
    cudaGetSymbolAddress((void**)&vp, g_V);
    cudaGetSymbolAddress((void**)&ap, g_A);

    __nv_bfloat16 *xhi, *xlo, *whi, *wlo, *ahi, *alo;
    cudaGetSymbolAddress((void**)&xhi, g_xhi);
    cudaGetSymbolAddress((void**)&xlo, g_xlo);
    cudaGetSymbolAddress((void**)&whi, g_whi);
    cudaGetSymbolAddress((void**)&wlo, g_wlo);
    cudaGetSymbolAddress((void**)&ahi, g_ahi);
    cudaGetSymbolAddress((void**)&alo, g_alo);

    const size_t WSZ = (size_t)D_EMB * D_EMB;
    const int nx4 = (MROWS * D_EMB) / 4;
    const int nw4 = (int)(WSZ / 4);

    // splits
    split_kernel<<<(nx4 + 255) / 256, 256>>>(x, xhi, xlo, nx4);
    split_kernel<<<(nw4 + 255) / 256, 256>>>(Wq, whi + 0 * WSZ, wlo + 0 * WSZ, nw4);
    split_kernel<<<(nw4 + 255) / 256, 256>>>(Wk, whi + 1 * WSZ, wlo + 1 * WSZ, nw4);
    split_kernel<<<(nw4 + 255) / 256, 256>>>(Wv, whi + 2 * WSZ, wlo + 2 * WSZ, nw4);
    split_kernel<<<(nw4 + 255) / 256, 256>>>(Wo, whi + 3 * WSZ, wlo + 3 * WSZ, nw4);

    dim3 gg(D_EMB / BN, MROWS / BM);   // (16, 32)
    gemm_bf16x3<<<gg, 256>>>(xhi, xlo, whi + 0 * WSZ, wlo + 0 * WSZ, qp, MROWS, D_EMB, D_EMB);
    gemm_bf16x3<<<gg, 256>>>(xhi, xlo, whi + 1 * WSZ, wlo + 1 * WSZ, kp, MROWS, D_EMB, D_EMB);
    gemm_bf16x3<<<gg, 256>>>(xhi, xlo, whi + 2 * WSZ, wlo + 2 * WSZ, vp, MROWS, D_EMB, D_EMB);

    rope_kernel<<<2048, 256>>>(qp, kp);
    lam_kernel<<<1, 64>>>(lq1, lk1, lq2, lk2);

    cudaFuncSetAttribute(flash_kernel, cudaFuncAttributeMaxDynamicSharedMemorySize,
                         FLASH_SMEM_BYTES);
    flash_kernel<<<dim3(32, NHEAD, BATCH), 256, FLASH_SMEM_BYTES>>>(qp, kp, vp, lnw, lnb, ap);

    split_kernel<<<(nx4 + 255) / 256, 256>>>(ap, ahi, alo, nx4);
    gemm_bf16x3<<<gg, 256>>>(ahi, alo, whi + 3 * WSZ, wlo + 3 * WSZ, out, MROWS, D_EMB, D_EMB);
}

// round 3
// speedup vs baseline: 2.2209x; 1.5156x over previous
#include <cuda_runtime.h>
#include <cuda_bf16.h>
#include <cstdint>
#include <cstddef>

#define S_LEN 2048
#define D_EMB 2048
#define NHEAD 16
#define HDIM 64
#define DVDIM 128
#define BATCH 2
#define MROWS (BATCH * S_LEN)   // 4096

#define LAMBDA_INIT_F 0.78360576653162435f
#define ONE_MINUS_LI_F 0.21639423346837565f

// ---------------- scratch (device globals) -------------------------------
__device__ float g_Q[(size_t)MROWS * D_EMB];
__device__ float g_K[(size_t)MROWS * D_EMB];
__device__ float g_V[(size_t)MROWS * D_EMB];
__device__ float g_A[(size_t)MROWS * D_EMB];
__device__ float g_lam;

__device__ __nv_bfloat16 g_xhi[(size_t)MROWS * D_EMB];
__device__ __nv_bfloat16 g_xlo[(size_t)MROWS * D_EMB];
__device__ __nv_bfloat16 g_whi[4][(size_t)D_EMB * D_EMB];
__device__ __nv_bfloat16 g_wlo[4][(size_t)D_EMB * D_EMB];
__device__ __nv_bfloat16 g_ahi[(size_t)MROWS * D_EMB];
__device__ __nv_bfloat16 g_alo[(size_t)MROWS * D_EMB];

__device__ __nv_bfloat16 g_Qhi[(size_t)MROWS * D_EMB];
__device__ __nv_bfloat16 g_Qlo[(size_t)MROWS * D_EMB];
__device__ __nv_bfloat16 g_Khi[(size_t)MROWS * D_EMB];
__device__ __nv_bfloat16 g_Klo[(size_t)MROWS * D_EMB];
__device__ __nv_bfloat16 g_Vhi[(size_t)MROWS * D_EMB];
__device__ __nv_bfloat16 g_Vlo[(size_t)MROWS * D_EMB];

// ---------------- common PTX helpers --------------------------------------
__device__ __forceinline__ uint32_t smem_u32(const void* p) {
    return (uint32_t)__cvta_generic_to_shared(p);
}
__device__ __forceinline__ void cp16(uint32_t s, const void* g) {
    asm volatile("cp.async.ca.shared.global [%0], [%1], 16;" :: "r"(s), "l"(g));
}
__device__ __forceinline__ void ldmx4(uint32_t r[4], uint32_t addr) {
    asm volatile("ldmatrix.sync.aligned.m8n8.x4.shared.b16 {%0,%1,%2,%3}, [%4];"
        : "=r"(r[0]), "=r"(r[1]), "=r"(r[2]), "=r"(r[3]) : "r"(addr));
}
__device__ __forceinline__ void ldmx2t(uint32_t r[2], uint32_t addr) {
    asm volatile("ldmatrix.sync.aligned.m8n8.x2.trans.shared.b16 {%0,%1}, [%2];"
        : "=r"(r[0]), "=r"(r[1]) : "r"(addr));
}
__device__ __forceinline__ void mma_bf16(float c[4], const uint32_t a[4], const uint32_t b[2]) {
    asm volatile("mma.sync.aligned.m16n8k16.row.col.f32.bf16.bf16.f32 "
        "{%0,%1,%2,%3}, {%4,%5,%6,%7}, {%8,%9}, {%0,%1,%2,%3};"
        : "+f"(c[0]), "+f"(c[1]), "+f"(c[2]), "+f"(c[3])
        : "r"(a[0]), "r"(a[1]), "r"(a[2]), "r"(a[3]), "r"(b[0]), "r"(b[1]));
}
__device__ __forceinline__ uint32_t pack_bf16(float lo, float hi) {
    uint32_t r;
    asm("cvt.rn.bf16x2.f32 %0, %1, %2;" : "=r"(r) : "f"(hi), "f"(lo));
    return r;
}
// fast exp on FMA pipe: exp(x) for x<=0, clamped
__device__ __forceinline__ float fexp(float x) {
    float t = fmaxf(x, -60.0f) * 1.44269504088896340736f;
    float fi = floorf(t);
    float f = t - fi;
    float p = 1.53964252399628e-4f;
    p = p * f + 1.33336498402e-3f;
    p = p * f + 9.61817668305e-3f;
    p = p * f + 5.55041086648e-2f;
    p = p * f + 2.40226506959101e-1f;
    p = p * f + 6.93147180559945e-1f;
    p = p * f + 1.0f;
    return __int_as_float(__float_as_int(p) + (((int)fi) << 23));
}

// =================== fp32 -> (bf16 hi, bf16 lo) split ====================
__global__ void split_kernel(const float* __restrict__ in,
                             __nv_bfloat16* __restrict__ hi,
                             __nv_bfloat16* __restrict__ lo, int n4)
{
    int i = blockIdx.x * blockDim.x + threadIdx.x;
    if (i >= n4) return;
    float4 v = ((const float4*)in)[i];
    __nv_bfloat16 hx = __float2bfloat16(v.x);
    __nv_bfloat16 hy = __float2bfloat16(v.y);
    __nv_bfloat16 hz = __float2bfloat16(v.z);
    __nv_bfloat16 hw = __float2bfloat16(v.w);
    __nv_bfloat16 lx = __float2bfloat16(v.x - __bfloat162float(hx));
    __nv_bfloat16 ly = __float2bfloat16(v.y - __bfloat162float(hy));
    __nv_bfloat16 lz = __float2bfloat16(v.z - __bfloat162float(hz));
    __nv_bfloat16 lw = __float2bfloat16(v.w - __bfloat162float(hw));
    __nv_bfloat162* H = (__nv_bfloat162*)hi;
    __nv_bfloat162* L = (__nv_bfloat162*)lo;
    H[2 * i]     = __halves2bfloat162(hx, hy);
    H[2 * i + 1] = __halves2bfloat162(hz, hw);
    L[2 * i]     = __halves2bfloat162(lx, ly);
    L[2 * i + 1] = __halves2bfloat162(lz, lw);
}

// =================== tensor-core GEMM (bf16 x3 split) ====================
#define BM 128
#define BN 128
#define BK 16
#define A_PITCH_B 48
#define B_PITCH_B 272
#define OFF_AHI 0
#define OFF_ALO (BM * A_PITCH_B)
#define OFF_BHI (2 * BM * A_PITCH_B)
#define OFF_BLO (OFF_BHI + BK * B_PITCH_B)
#define STAGE_BYTES (OFF_BLO + BK * B_PITCH_B)

__global__ __launch_bounds__(256)
void gemm_bf16x3(const __nv_bfloat16* __restrict__ Ahi, const __nv_bfloat16* __restrict__ Alo,
                 const __nv_bfloat16* __restrict__ Bhi, const __nv_bfloat16* __restrict__ Blo,
                 float* __restrict__ C, int M, int N, int K)
{
    __shared__ __align__(16) uint8_t sm[2][STAGE_BYTES];
    const int tid = threadIdx.x;
    const int m0 = blockIdx.y * BM;
    const int n0 = blockIdx.x * BN;
    const uint32_t sbase = smem_u32(&sm[0][0]);

    const int a_r = tid >> 1;
    const int a_c = (tid & 1) * 8;
    const int b_r = tid >> 4;
    const int b_c = (tid & 15) * 8;

    const __nv_bfloat16* gAhi = Ahi + (size_t)(m0 + a_r) * K + a_c;
    const __nv_bfloat16* gAlo = Alo + (size_t)(m0 + a_r) * K + a_c;
    const __nv_bfloat16* gBhi = Bhi + (size_t)b_r * N + n0 + b_c;
    const __nv_bfloat16* gBlo = Blo + (size_t)b_r * N + n0 + b_c;
    const uint32_t sA_off = a_r * A_PITCH_B + a_c * 2;
    const uint32_t sB_off = b_r * B_PITCH_B + b_c * 2;

    const int lane = tid & 31;
    const int wid = tid >> 5;
    const int wm = wid & 3;
    const int wn = wid >> 2;

    const int ar = wm * 32 + (lane & 7) + ((lane >> 3) & 1) * 8;
    const int ak = ((lane >> 4) & 1) * 8;
    const uint32_t aoff0 = ar * A_PITCH_B + ak * 2;
    const uint32_t aoff1 = aoff0 + 16 * A_PITCH_B;
    const uint32_t boff = (lane & 15) * B_PITCH_B + (wn * 64) * 2;

    float acc[2][8][4];
#pragma unroll
    for (int i = 0; i < 2; i++)
#pragma unroll
        for (int j = 0; j < 8; j++)
#pragma unroll
            for (int l = 0; l < 4; l++) acc[i][j][l] = 0.f;

    const int KT = K / BK;
    {
        uint32_t s = sbase;
        cp16(s + OFF_AHI + sA_off, gAhi);
        cp16(s + OFF_ALO + sA_off, gAlo);
        cp16(s + OFF_BHI + sB_off, gBhi);
        cp16(s + OFF_BLO + sB_off, gBlo);
        asm volatile("cp.async.commit_group;");
    }

    for (int t = 0; t < KT; t++) {
        if (t + 1 < KT) {
            uint32_t s = sbase + ((t + 1) & 1) * STAGE_BYTES;
            cp16(s + OFF_AHI + sA_off, gAhi + (size_t)(t + 1) * BK);
            cp16(s + OFF_ALO + sA_off, gAlo + (size_t)(t + 1) * BK);
            cp16(s + OFF_BHI + sB_off, gBhi + (size_t)(t + 1) * BK * N);
            cp16(s + OFF_BLO + sB_off, gBlo + (size_t)(t + 1) * BK * N);
            asm volatile("cp.async.commit_group;");
            asm volatile("cp.async.wait_group 1;");
        } else {
            asm volatile("cp.async.wait_group 0;");
        }
        __syncthreads();

        uint32_t s = sbase + (t & 1) * STAGE_BYTES;
        uint32_t ah[2][4], al[2][4], bh[8][2], bl[8][2];
        ldmx4(ah[0], s + OFF_AHI + aoff0);
        ldmx4(ah[1], s + OFF_AHI + aoff1);
        ldmx4(al[0], s + OFF_ALO + aoff0);
        ldmx4(al[1], s + OFF_ALO + aoff1);
#pragma unroll
        for (int nt = 0; nt < 8; nt++) {
            ldmx2t(bh[nt], s + OFF_BHI + boff + nt * 16);
            ldmx2t(bl[nt], s + OFF_BLO + boff + nt * 16);
        }
#pragma unroll
        for (int mt = 0; mt < 2; mt++)
#pragma unroll
            for (int nt = 0; nt < 8; nt++) {
                mma_bf16(acc[mt][nt], ah[mt], bh[nt]);
                mma_bf16(acc[mt][nt], ah[mt], bl[nt]);
                mma_bf16(acc[mt][nt], al[mt], bh[nt]);
            }
        __syncthreads();
    }

    const int gid = lane >> 2, tig = lane & 3;
#pragma unroll
    for (int mt = 0; mt < 2; mt++) {
        int row = m0 + wm * 32 + mt * 16 + gid;
#pragma unroll
        for (int nt = 0; nt < 8; nt++) {
            int col = n0 + wn * 64 + nt * 8 + 2 * tig;
            *(float2*)&C[(size_t)row * N + col] = make_float2(acc[mt][nt][0], acc[mt][nt][1]);
            *(float2*)&C[(size_t)(row + 8) * N + col] = make_float2(acc[mt][nt][2], acc[mt][nt][3]);
        }
    }
}

// ---------------- RoPE + bf16 hi/lo split (Q,K) ---------------------------
__global__ void rope_split_kernel(const float* __restrict__ Q, const float* __restrict__ K,
                                  __nv_bfloat16* __restrict__ Qhi, __nv_bfloat16* __restrict__ Qlo,
                                  __nv_bfloat16* __restrict__ Khi, __nv_bfloat16* __restrict__ Klo)
{
    const long total = (long)MROWS * (D_EMB / 2);
    const float LN1E4_OVER_32 = 9.210340371976184f / 32.0f;
    for (long p = (long)blockIdx.x * blockDim.x + threadIdx.x; p < total;
         p += (long)gridDim.x * blockDim.x) {
        int pcol = (int)(p & (D_EMB / 2 - 1));
        long row = p >> 10;
        int s = (int)(row & (S_LEN - 1));
        int j = pcol & 31;
        float inv = expf(-(float)j * LN1E4_OVER_32);
        float ang = (float)s * inv;
        float sn, cs;
        sincosf(ang, &sn, &cs);
        size_t idx = (size_t)row * D_EMB + 2 * pcol;
        size_t pi = (size_t)row * (D_EMB / 2) + pcol;

        float q0 = Q[idx], q1 = Q[idx + 1];
        float rq0 = q0 * cs - q1 * sn;
        float rq1 = q1 * cs + q0 * sn;
        __nv_bfloat16 qh0 = __float2bfloat16(rq0);
        __nv_bfloat16 qh1 = __float2bfloat16(rq1);
        ((__nv_bfloat162*)Qhi)[pi] = __halves2bfloat162(qh0, qh1);
        ((__nv_bfloat162*)Qlo)[pi] = __halves2bfloat162(
            __float2bfloat16(rq0 - __bfloat162float(qh0)),
            __float2bfloat16(rq1 - __bfloat162float(qh1)));

        float k0 = K[idx], k1 = K[idx + 1];
        float rk0 = k0 * cs - k1 * sn;
        float rk1 = k1 * cs + k0 * sn;
        __nv_bfloat16 kh0 = __float2bfloat16(rk0);
        __nv_bfloat16 kh1 = __float2bfloat16(rk1);
        ((__nv_bfloat162*)Khi)[pi] = __halves2bfloat162(kh0, kh1);
        ((__nv_bfloat162*)Klo)[pi] = __halves2bfloat162(
            __float2bfloat16(rk0 - __bfloat162float(kh0)),
            __float2bfloat16(rk1 - __bfloat162float(kh1)));
    }
}

// ---------------- lambda scalar ------------------------------------------
__global__ void lam_kernel(const float* __restrict__ lq1, const float* __restrict__ lk1,
                           const float* __restrict__ lq2, const float* __restrict__ lk2)
{
    __shared__ float s1[64], s2[64];
    int t = threadIdx.x;
    s1[t] = lq1[t] * lk1[t];
    s2[t] = lq2[t] * lk2[t];
    __syncthreads();
    if (t == 0) {
        float d1 = 0.f, d2 = 0.f;
        for (int i = 0; i < 64; i++) { d1 += s1[i]; d2 += s2[i]; }
        g_lam = expf(d1) - expf(d2) + LAMBDA_INIT_F;
    }
}

// ================= MMA dual-branch flash attention ========================
#define PQB 144                 // Q/K smem pitch bytes (72 bf16)
#define PVB 272                 // V smem pitch bytes (136 bf16)
#define QK_TILE (64 * PQB)      // 9216
#define V_TILE  (64 * PVB)      // 17408
#define OFF_SQ 0
#define OFF_SK (4 * QK_TILE)    // 36864
#define OFF_SV (8 * QK_TILE)    // 73728
#define FL_SMEM (OFF_SV + 2 * V_TILE)  // 108544

__global__ __launch_bounds__(256, 1)
void flash_mma_kernel(const __nv_bfloat16* __restrict__ Qhi, const __nv_bfloat16* __restrict__ Qlo,
                      const __nv_bfloat16* __restrict__ Khi, const __nv_bfloat16* __restrict__ Klo,
                      const __nv_bfloat16* __restrict__ Vhi, const __nv_bfloat16* __restrict__ Vlo,
                      const float* __restrict__ lnw, const float* __restrict__ lnb,
                      float* __restrict__ Aout)
{
    extern __shared__ __align__(16) uint8_t smraw[];
    const uint32_t sbase = smem_u32(smraw);
    float* sOut = (float*)(smraw + OFF_SK);   // overlays K region after loop

    const int tid = threadIdx.x;
    const int lane = tid & 31;
    const int wid = tid >> 5;
    const int br = wid >> 2;            // 0: branch1 warps, 1: branch2
    const int rbase = (wid & 3) * 16;   // 16 q-rows per warp
    const int g = lane >> 2;
    const int tg = lane & 3;

    const int qt = blockIdx.x;
    const int h = blockIdx.y;
    const int b = blockIdx.z;
    const int q0t = qt * 64;
    const size_t rowBase = (size_t)b * S_LEN;
    const int colH = h * 128;

    // ---- Q tiles: 4 (br x hl), cp.async ----
#pragma unroll
    for (int it = 0; it < 8; it++) {
        int idx = tid + 256 * it;
        int ch = idx & 7, r = (idx >> 3) & 63, t = idx >> 9;
        const __nv_bfloat16* src = ((t & 1) ? Qlo : Qhi)
            + (rowBase + q0t + r) * D_EMB + colH + (t >> 1) * 64 + ch * 8;
        cp16(sbase + OFF_SQ + t * QK_TILE + r * PQB + ch * 16, src);
    }
    asm volatile("cp.async.commit_group;");
    asm volatile("cp.async.wait_group 0;");
    __syncthreads();

    // ---- Q fragments (persist in registers) ----
    uint32_t qh[4][4], ql[4][4];
    {
        uint32_t qoff = (uint32_t)(rbase + (lane & 15)) * PQB + ((lane >> 4) << 4);
        uint32_t bh_ = sbase + OFF_SQ + (br * 2) * QK_TILE;
#pragma unroll
        for (int s = 0; s < 4; s++) {
            ldmx4(qh[s], bh_ + qoff + s * 32);
            ldmx4(ql[s], bh_ + QK_TILE + qoff + s * 32);
        }
    }

    float o[16][4];
#pragma unroll
    for (int i = 0; i < 16; i++)
#pragma unroll
        for (int j = 0; j < 4; j++) o[i][j] = 0.f;
    float m_a = -1e30f, m_b = -1e30f, l_a = 0.f, l_b = 0.f;

    for (int kt = 0; kt <= qt; kt++) {
        __syncthreads();   // previous iter compute done before overwrite
        // ---- K tiles ----
#pragma unroll
        for (int it = 0; it < 8; it++) {
            int idx = tid + 256 * it;
            int ch = idx & 7, r = (idx >> 3) & 63, t = idx >> 9;
            const __nv_bfloat16* src = ((t & 1) ? Klo : Khi)
                + (rowBase + (size_t)kt * 64 + r) * D_EMB + colH + (t >> 1) * 64 + ch * 8;
            cp16(sbase + OFF_SK + t * QK_TILE + r * PQB + ch * 16, src);
        }
        // ---- V tiles ----
#pragma unroll
        for (int it = 0; it < 8; it++) {
            int idx = tid + 256 * it;
            int ch = idx & 15, r = (idx >> 4) & 63, t = idx >> 10;
            const __nv_bfloat16* src = (t ? Vlo : Vhi)
                + (rowBase + (size_t)kt * 64 + r) * D_EMB + colH + ch * 8;
            cp16(sbase + OFF_SV + t * V_TILE + r * PVB + ch * 16, src);
        }
        asm volatile("cp.async.commit_group;");
        asm volatile("cp.async.wait_group 0;");
        __syncthreads();

        // ---- scores: 16 x 64 per warp (own branch) ----
        float sc[8][4];
#pragma unroll
        for (int i = 0; i < 8; i++)
#pragma unroll
            for (int j = 0; j < 4; j++) sc[i][j] = 0.f;

        const uint32_t kbh = sbase + OFF_SK + (br * 2) * QK_TILE;
        const uint32_t koff = (uint32_t)(lane & 7) * PQB + ((lane >> 3) << 4);
#pragma unroll
        for (int nt = 0; nt < 8; nt++) {
            uint32_t a = koff + (uint32_t)nt * 8 * PQB;
            uint32_t kh0[4], kh1[4], kl0[4], kl1[4];
            ldmx4(kh0, kbh + a);
            ldmx4(kh1, kbh + a + 64);
            ldmx4(kl0, kbh + QK_TILE + a);
            ldmx4(kl1, kbh + QK_TILE + a + 64);
            mma_bf16(sc[nt], qh[0], &kh0[0]);
            mma_bf16(sc[nt], ql[0], &kh0[0]);
            mma_bf16(sc[nt], qh[0], &kl0[0]);
            mma_bf16(sc[nt], qh[1], &kh0[2]);
            mma_bf16(sc[nt], ql[1], &kh0[2]);
            mma_bf16(sc[nt], qh[1], &kl0[2]);
            mma_bf16(sc[nt], qh[2], &kh1[0]);
            mma_bf16(sc[nt], ql[2], &kh1[0]);
            mma_bf16(sc[nt], qh[2], &kl1[0]);
            mma_bf16(sc[nt], qh[3], &kh1[2]);
            mma_bf16(sc[nt], ql[3], &kh1[2]);
            mma_bf16(sc[nt], qh[3], &kl1[2]);
        }

        // ---- scale, mask, row max ----
        const bool diag = (kt == qt);
        float mxa = -1e30f, mxb = -1e30f;
#pragma unroll
        for (int nt = 0; nt < 8; nt++) {
            int c0 = nt * 8 + 2 * tg;
#pragma unroll
            for (int e = 0; e < 4; e++) {
                int row = rbase + g + ((e >> 1) << 3);
                int col = c0 + (e & 1);
                float v = sc[nt][e] * 0.125f;
                if (diag && col > row) v = -1e30f;
                sc[nt][e] = v;
            }
            mxa = fmaxf(mxa, fmaxf(sc[nt][0], sc[nt][1]));
            mxb = fmaxf(mxb, fmaxf(sc[nt][2], sc[nt][3]));
        }
        mxa = fmaxf(mxa, __shfl_xor_sync(0xffffffffu, mxa, 1));
        mxa = fmaxf(mxa, __shfl_xor_sync(0xffffffffu, mxa, 2));
        mxb = fmaxf(mxb, __shfl_xor_sync(0xffffffffu, mxb, 1));
        mxb = fmaxf(mxb, __shfl_xor_sync(0xffffffffu, mxb, 2));
        float mna = fmaxf(m_a, mxa), mnb = fmaxf(m_b, mxb);
        float alf_a = fexp(m_a - mna), alf_b = fexp(m_b - mnb);
        m_a = mna; m_b = mnb;

        // ---- P = exp(S - m) -> bf16 hi/lo A-fragments (in registers) ----
        float suma = 0.f, sumb = 0.f;
        uint32_t ph[4][4], pl[4][4];
#pragma unroll
        for (int s2 = 0; s2 < 4; s2++) {
#pragma unroll
            for (int hf = 0; hf < 2; hf++) {
                int nt = 2 * s2 + hf;
                float p0 = fexp(sc[nt][0] - m_a);
                float p1 = fexp(sc[nt][1] - m_a);
                float p2 = fexp(sc[nt][2] - m_b);
                float p3 = fexp(sc[nt][3] - m_b);
                suma += p0 + p1; sumb += p2 + p3;
                __nv_bfloat16 h0 = __float2bfloat16(p0);
                __nv_bfloat16 h1 = __float2bfloat16(p1);
                __nv_bfloat16 h2 = __float2bfloat16(p2);
                __nv_bfloat16 h3 = __float2bfloat16(p3);
                __nv_bfloat162 t01 = __halves2bfloat162(h0, h1);
                __nv_bfloat162 t23 = __halves2bfloat162(h2, h3);
                ph[s2][hf * 2 + 0] = *(uint32_t*)&t01;
                ph[s2][hf * 2 + 1] = *(uint32_t*)&t23;
                pl[s2][hf * 2 + 0] = pack_bf16(p0 - __bfloat162float(h0),
                                               p1 - __bfloat162float(h1));
                pl[s2][hf * 2 + 1] = pack_bf16(p2 - __bfloat162float(h2),
                                               p3 - __bfloat162float(h3));
            }
        }
        suma += __shfl_xor_sync(0xffffffffu, suma, 1);
        suma += __shfl_xor_sync(0xffffffffu, suma, 2);
        sumb += __shfl_xor_sync(0xffffffffu, sumb, 1);
        sumb += __shfl_xor_sync(0xffffffffu, sumb, 2);
        l_a = alf_a * l_a + suma;
        l_b = alf_b * l_b + sumb;

        // ---- rescale O ----
#pragma unroll
        for (int vt = 0; vt < 16; vt++) {
            o[vt][0] *= alf_a; o[vt][1] *= alf_a;
            o[vt][2] *= alf_b; o[vt][3] *= alf_b;
        }

        // ---- O += P V ----
        const uint32_t vb = sbase + OFF_SV;
        const uint32_t vrow = (uint32_t)(lane & 15) * PVB;
#pragma unroll
        for (int vt = 0; vt < 16; vt++) {
#pragma unroll
            for (int s2 = 0; s2 < 4; s2++) {
                uint32_t addr = (uint32_t)(s2 * 16) * PVB + vrow + vt * 16;
                uint32_t bh[2], bl[2];
                ldmx2t(bh, vb + addr);
                ldmx2t(bl, vb + V_TILE + addr);
                mma_bf16(o[vt], ph[s2], bh);
                mma_bf16(o[vt], pl[s2], bh);
                mma_bf16(o[vt], ph[s2], bl);
            }
        }
    }

    __syncthreads();
    float lam = g_lam;
    float ra = 1.0f / l_a, rb = 1.0f / l_b;

    if (br == 0) {
#pragma unroll
        for (int vt = 0; vt < 16; vt++) {
            int c = vt * 8 + 2 * tg;
            *(float2*)&sOut[(rbase + g) * 128 + c] = make_float2(o[vt][0] * ra, o[vt][1] * ra);
            *(float2*)&sOut[(rbase + g + 8) * 128 + c] = make_float2(o[vt][2] * rb, o[vt][3] * rb);
        }
    }
    __syncthreads();
    if (br == 1) {
#pragma unroll
        for (int vt = 0; vt < 16; vt++) {
            int c = vt * 8 + 2 * tg;
            float2* p0 = (float2*)&sOut[(rbase + g) * 128 + c];
            float2 v0 = *p0;
            v0.x -= lam * o[vt][0] * ra; v0.y -= lam * o[vt][1] * ra;
            *p0 = v0;
            float2* p1 = (float2*)&sOut[(rbase + g + 8) * 128 + c];
            float2 v1 = *p1;
            v1.x -= lam * o[vt][2] * rb; v1.y -= lam * o[vt][3] * rb;
            *p1 = v1;
        }
    }
    __syncthreads();

    // ---- RMSNorm + scale + write ----
    {
        int r = tid >> 2;
        int q4 = tid & 3;
        float ss = 0.f;
#pragma unroll
        for (int u = 0; u < 32; u++) {
            float v = sOut[r * 128 + q4 * 32 + u];
            ss += v * v;
        }
        ss += __shfl_xor_sync(0xffffffffu, ss, 1);
        ss += __shfl_xor_sync(0xffffffffu, ss, 2);
        float rn = rsqrtf(ss * (1.0f / 128.0f) + 1e-8f);
        size_t outrow = (rowBase + q0t + r) * D_EMB + colH;
#pragma unroll
        for (int u = 0; u < 32; u++) {
            int e = q4 * 32 + u;
            Aout[outrow + e] = (sOut[r * 128 + e] * rn * lnw[e] + lnb[e]) * ONE_MINUS_LI_F;
        }
    }
}

// ---------------- launch ---------------------------------------------------
extern "C" void kernel_launch(void* const* d_in, const int* in_sizes, int n_in,
                              void* d_out, int out_size)
{
    (void)in_sizes; (void)n_in; (void)out_size;
    const float* x   = (const float*)d_in[0];
    const float* Wq  = (const float*)d_in[1];
    const float* Wk  = (const float*)d_in[2];
    const float* Wv  = (const float*)d_in[3];
    const float* Wo  = (const float*)d_in[4];
    const float* lq1 = (const float*)d_in[5];
    const float* lk1 = (const float*)d_in[6];
    const float* lq2 = (const float*)d_in[7];
    const float* lk2 = (const float*)d_in[8];
    const float* lnw = (const float*)d_in[9];
    const float* lnb = (const float*)d_in[10];
    float* out = (float*)d_out;

    float *qp, *kp, *vp, *ap;
    cudaGetSymbolAddress((void**)&qp, g_Q);
    cudaGetSymbolAddress((void**)&kp, g_K);
    cudaGetSymbolAddress((void**)&vp, g_V);
    cudaGetSymbolAddress((void**)&ap, g_A);

    __nv_bfloat16 *xhi, *xlo, *whi, *wlo, *ahi, *alo;
    __nv_bfloat16 *qhi, *qlo, *khi, *klo, *vhi, *vlo;
    cudaGetSymbolAddress((void**)&xhi, g_xhi);
    cudaGetSymbolAddress((void**)&xlo, g_xlo);
    cudaGetSymbolAddress((void**)&whi, g_whi);
    cudaGetSymbolAddress((void**)&wlo, g_wlo);
    cudaGetSymbolAddress((void**)&ahi, g_ahi);
    cudaGetSymbolAddress((void**)&alo, g_alo);
    cudaGetSymbolAddress((void**)&qhi, g_Qhi);
    cudaGetSymbolAddress((void**)&qlo, g_Qlo);
    cudaGetSymbolAddress((void**)&khi, g_Khi);
    cudaGetSymbolAddress((void**)&klo, g_Klo);
    cudaGetSymbolAddress((void**)&vhi, g_Vhi);
    cudaGetSymbolAddress((void**)&vlo, g_Vlo);

    const size_t WSZ = (size_t)D_EMB * D_EMB;
    const int nx4 = (MROWS * D_EMB) / 4;
    const int nw4 = (int)(WSZ / 4);

    split_kernel<<<(nx4 + 255) / 256, 256>>>(x, xhi, xlo, nx4);
    split_kernel<<<(nw4 + 255) / 256, 256>>>(Wq, whi + 0 * WSZ, wlo + 0 * WSZ, nw4);
    split_kernel<<<(nw4 + 255) / 256, 256>>>(Wk, whi + 1 * WSZ, wlo + 1 * WSZ, nw4);
    split_kernel<<<(nw4 + 255) / 256, 256>>>(Wv, whi + 2 * WSZ, wlo + 2 * WSZ, nw4);
    split_kernel<<<(nw4 + 255) / 256, 256>>>(Wo, whi + 3 * WSZ, wlo + 3 * WSZ, nw4);

    dim3 gg(D_EMB / BN, MROWS / BM);
    gemm_bf16x3<<<gg, 256>>>(xhi, xlo, whi + 0 * WSZ, wlo + 0 * WSZ, qp, MROWS, D_EMB, D_EMB);
    gemm_bf16x3<<<gg, 256>>>(xhi, xlo, whi + 1 * WSZ, wlo + 1 * WSZ, kp, MROWS, D_EMB, D_EMB);
    gemm_bf16x3<<<gg, 256>>>(xhi, xlo, whi + 2 * WSZ, wlo + 2 * WSZ, vp, MROWS, D_EMB, D_EMB);

    rope_split_kernel<<<2048, 256>>>(qp, kp, qhi, qlo, khi, klo);
    split_kernel<<<(nx4 + 255) / 256, 256>>>(vp, vhi, vlo, nx4);
    lam_kernel<<<1, 64>>>(lq1, lk1, lq2, lk2);

    cudaFuncSetAttribute(flash_mma_kernel, cudaFuncAttributeMaxDynamicSharedMemorySize, FL_SMEM);
    flash_mma_kernel<<<dim3(32, NHEAD, BATCH), 256, FL_SMEM>>>(
        qhi, qlo, khi, klo, vhi, vlo, lnw, lnb, ap);

    split_kernel<<<(nx4 + 255) / 256, 256>>>(ap, ahi, alo, nx4);
    gemm_bf16x3<<<gg, 256>>>(ahi, alo, whi + 3 * WSZ, wlo + 3 * WSZ, out, MROWS, D_EMB, D_EMB);
}